// round 3
// baseline (speedup 1.0000x reference)
#include <cuda_runtime.h>
#include <cuda_bf16.h>

#define BB   512
#define LL   1000
#define HH   128
#define NCTA 86
#define NT   256
#define MR   6

typedef unsigned long long ull;

__device__ __forceinline__ ull ffma2(ull a, ull b, ull c) {
    ull d;
    asm("fma.rn.f32x2 %0, %1, %2, %3;" : "=l"(d) : "l"(a), "l"(b), "l"(c));
    return d;
}
__device__ __forceinline__ float flo(ull v) { return __uint_as_float((unsigned)v); }
__device__ __forceinline__ float fhi(ull v) { return __uint_as_float((unsigned)(v >> 32)); }

__device__ __forceinline__ float sig_(float x) {
    float e, r;
    asm("ex2.approx.f32 %0, %1;" : "=f"(e) : "f"(-1.4426950408889634f * x));
    asm("rcp.approx.f32 %0, %1;" : "=f"(r) : "f"(1.0f + e));
    return r;
}
__device__ __forceinline__ float tnh_(float x) { return fmaf(2.0f, sig_(2.0f * x), -1.0f); }

__global__ void __launch_bounds__(NT, 1) lstm_persist(
    const float* __restrict__ x,
    const float* __restrict__ w_ih1, const float* __restrict__ w_hh1,
    const float* __restrict__ b_ih1, const float* __restrict__ b_hh1,
    const float* __restrict__ w_ih2, const float* __restrict__ w_hh2,
    const float* __restrict__ b_ih2, const float* __restrict__ b_hh2,
    const float* __restrict__ w_lin, const float* __restrict__ b_lin,
    float* __restrict__ out)
{
    __shared__ __align__(16) float h1s[MR][HH];
    __shared__ __align__(16) float h2s[MR][HH];
    __shared__ __align__(16) float gbuf[MR][4 * HH];
    __shared__ float bs1[4 * HH], bs2[4 * HH], wi1[4 * HH], wls[HH], xs[MR];

    const int tid  = threadIdx.x;
    const int row0 = blockIdx.x * MR;

    for (int i = tid; i < 4 * HH; i += NT) {
        bs1[i] = b_ih1[i] + b_hh1[i];
        bs2[i] = b_ih2[i] + b_hh2[i];
        wi1[i] = w_ih1[i];
    }
    for (int i = tid; i < HH; i += NT) wls[i] = w_lin[i];
    for (int i = tid; i < MR * HH; i += NT) {
        (&h1s[0][0])[i] = 0.0f;
        (&h2s[0][0])[i] = 0.0f;
    }
    if (tid < MR) xs[tid] = (row0 + tid < BB) ? x[(row0 + tid) * LL] : 0.0f;

    float c1[3] = {0.f, 0.f, 0.f};
    float c2[3] = {0.f, 0.f, 0.f};
    const float blin = b_lin[0];

    const int j0 = tid, j1 = tid + NT;
    const float* wh1a = w_hh1 + j0 * HH;
    const float* wh1b = w_hh1 + j1 * HH;
    const float* wi2a = w_ih2 + j0 * HH;
    const float* wi2b = w_ih2 + j1 * HH;
    const float* wh2a = w_hh2 + j0 * HH;
    const float* wh2b = w_hh2 + j1 * HH;

    __syncthreads();

    for (int t = 0; t < LL; t++) {
        // readout for step t-1 (h2s stable until phase D of this step)
        if (t > 0 && tid < MR && row0 + tid < BB) {
            float s = blin;
#pragma unroll 8
            for (int u = 0; u < HH; u++) s = fmaf(h2s[tid][u], wls[u], s);
            out[(row0 + tid) * LL + (t - 1)] = s;
        }

        // ---- Phase A: layer-1 gates = h1 @ Whh1^T (+ wih1*x + b) ----
        {
            ull acc[2][MR];
#pragma unroll
            for (int r = 0; r < MR; r++) { acc[0][r] = 0ull; acc[1][r] = 0ull; }
#pragma unroll 4
            for (int kk = 0; kk < 16; kk++) {
                ulonglong2 ha[MR], hb[MR];
#pragma unroll
                for (int r = 0; r < MR; r++) {
                    const ulonglong2* hp = (const ulonglong2*)&h1s[r][kk * 8];
                    ha[r] = hp[0]; hb[r] = hp[1];
                }
                ulonglong2 wa0 = *(const ulonglong2*)(wh1a + kk * 8);
                ulonglong2 wa1 = *(const ulonglong2*)(wh1a + kk * 8 + 4);
                ulonglong2 wb0 = *(const ulonglong2*)(wh1b + kk * 8);
                ulonglong2 wb1 = *(const ulonglong2*)(wh1b + kk * 8 + 4);
#pragma unroll
                for (int r = 0; r < MR; r++) {
                    acc[0][r] = ffma2(wa0.x, ha[r].x, acc[0][r]);
                    acc[0][r] = ffma2(wa0.y, ha[r].y, acc[0][r]);
                    acc[0][r] = ffma2(wa1.x, hb[r].x, acc[0][r]);
                    acc[0][r] = ffma2(wa1.y, hb[r].y, acc[0][r]);
                    acc[1][r] = ffma2(wb0.x, ha[r].x, acc[1][r]);
                    acc[1][r] = ffma2(wb0.y, ha[r].y, acc[1][r]);
                    acc[1][r] = ffma2(wb1.x, hb[r].x, acc[1][r]);
                    acc[1][r] = ffma2(wb1.y, hb[r].y, acc[1][r]);
                }
            }
#pragma unroll
            for (int r = 0; r < MR; r++) {
                gbuf[r][j0] = flo(acc[0][r]) + fhi(acc[0][r]) + bs1[j0] + wi1[j0] * xs[r];
                gbuf[r][j1] = flo(acc[1][r]) + fhi(acc[1][r]) + bs1[j1] + wi1[j1] * xs[r];
            }
        }
        __syncthreads();

        // ---- Phase B: layer-1 activations ----
#pragma unroll
        for (int s = 0; s < 3; s++) {
            int idx = tid + NT * s;
            int r = idx >> 7, u = idx & (HH - 1);
            float iv = sig_(gbuf[r][u]);
            float fv = sig_(gbuf[r][HH + u]);
            float gv = tnh_(gbuf[r][2 * HH + u]);
            float ov = sig_(gbuf[r][3 * HH + u]);
            c1[s] = fmaf(fv, c1[s], iv * gv);
            h1s[r][u] = ov * tnh_(c1[s]);
        }
        __syncthreads();

        // ---- Phase C: layer-2 gates = h1 @ Wih2^T + h2 @ Whh2^T (+ b) ----
        {
            ull acc[2][MR];
#pragma unroll
            for (int r = 0; r < MR; r++) { acc[0][r] = 0ull; acc[1][r] = 0ull; }
#pragma unroll 4
            for (int kk = 0; kk < 16; kk++) {
                ulonglong2 ha[MR], hb[MR];
#pragma unroll
                for (int r = 0; r < MR; r++) {
                    const ulonglong2* hp = (const ulonglong2*)&h1s[r][kk * 8];
                    ha[r] = hp[0]; hb[r] = hp[1];
                }
                ulonglong2 wa0 = *(const ulonglong2*)(wi2a + kk * 8);
                ulonglong2 wa1 = *(const ulonglong2*)(wi2a + kk * 8 + 4);
                ulonglong2 wb0 = *(const ulonglong2*)(wi2b + kk * 8);
                ulonglong2 wb1 = *(const ulonglong2*)(wi2b + kk * 8 + 4);
#pragma unroll
                for (int r = 0; r < MR; r++) {
                    acc[0][r] = ffma2(wa0.x, ha[r].x, acc[0][r]);
                    acc[0][r] = ffma2(wa0.y, ha[r].y, acc[0][r]);
                    acc[0][r] = ffma2(wa1.x, hb[r].x, acc[0][r]);
                    acc[0][r] = ffma2(wa1.y, hb[r].y, acc[0][r]);
                    acc[1][r] = ffma2(wb0.x, ha[r].x, acc[1][r]);
                    acc[1][r] = ffma2(wb0.y, ha[r].y, acc[1][r]);
                    acc[1][r] = ffma2(wb1.x, hb[r].x, acc[1][r]);
                    acc[1][r] = ffma2(wb1.y, hb[r].y, acc[1][r]);
                }
            }
#pragma unroll 4
            for (int kk = 0; kk < 16; kk++) {
                ulonglong2 ha[MR], hb[MR];
#pragma unroll
                for (int r = 0; r < MR; r++) {
                    const ulonglong2* hp = (const ulonglong2*)&h2s[r][kk * 8];
                    ha[r] = hp[0]; hb[r] = hp[1];
                }
                ulonglong2 wa0 = *(const ulonglong2*)(wh2a + kk * 8);
                ulonglong2 wa1 = *(const ulonglong2*)(wh2a + kk * 8 + 4);
                ulonglong2 wb0 = *(const ulonglong2*)(wh2b + kk * 8);
                ulonglong2 wb1 = *(const ulonglong2*)(wh2b + kk * 8 + 4);
#pragma unroll
                for (int r = 0; r < MR; r++) {
                    acc[0][r] = ffma2(wa0.x, ha[r].x, acc[0][r]);
                    acc[0][r] = ffma2(wa0.y, ha[r].y, acc[0][r]);
                    acc[0][r] = ffma2(wa1.x, hb[r].x, acc[0][r]);
                    acc[0][r] = ffma2(wa1.y, hb[r].y, acc[0][r]);
                    acc[1][r] = ffma2(wb0.x, ha[r].x, acc[1][r]);
                    acc[1][r] = ffma2(wb0.y, ha[r].y, acc[1][r]);
                    acc[1][r] = ffma2(wb1.x, hb[r].x, acc[1][r]);
                    acc[1][r] = ffma2(wb1.y, hb[r].y, acc[1][r]);
                }
            }
#pragma unroll
            for (int r = 0; r < MR; r++) {
                gbuf[r][j0] = flo(acc[0][r]) + fhi(acc[0][r]) + bs2[j0];
                gbuf[r][j1] = flo(acc[1][r]) + fhi(acc[1][r]) + bs2[j1];
            }
        }
        __syncthreads();

        // ---- Phase D: layer-2 activations + x prefetch ----
#pragma unroll
        for (int s = 0; s < 3; s++) {
            int idx = tid + NT * s;
            int r = idx >> 7, u = idx & (HH - 1);
            float iv = sig_(gbuf[r][u]);
            float fv = sig_(gbuf[r][HH + u]);
            float gv = tnh_(gbuf[r][2 * HH + u]);
            float ov = sig_(gbuf[r][3 * HH + u]);
            c2[s] = fmaf(fv, c2[s], iv * gv);
            h2s[r][u] = ov * tnh_(c2[s]);
        }
        if (tid < MR)
            xs[tid] = (row0 + tid < BB && t + 1 < LL) ? x[(row0 + tid) * LL + t + 1] : 0.0f;
        __syncthreads();
    }

    // final readout (t = LL-1)
    if (tid < MR && row0 + tid < BB) {
        float s = blin;
#pragma unroll 8
        for (int u = 0; u < HH; u++) s = fmaf(h2s[tid][u], wls[u], s);
        out[(row0 + tid) * LL + (LL - 1)] = s;
    }
}

extern "C" void kernel_launch(void* const* d_in, const int* in_sizes, int n_in,
                              void* d_out, int out_size) {
    const float* x     = (const float*)d_in[0];
    const float* w_ih1 = (const float*)d_in[1];
    const float* w_hh1 = (const float*)d_in[2];
    const float* b_ih1 = (const float*)d_in[3];
    const float* b_hh1 = (const float*)d_in[4];
    const float* w_ih2 = (const float*)d_in[5];
    const float* w_hh2 = (const float*)d_in[6];
    const float* b_ih2 = (const float*)d_in[7];
    const float* b_hh2 = (const float*)d_in[8];
    const float* w_lin = (const float*)d_in[9];
    const float* b_lin = (const float*)d_in[10];
    float* out = (float*)d_out;

    lstm_persist<<<NCTA, NT>>>(x, w_ih1, w_hh1, b_ih1, b_hh1,
                               w_ih2, w_hh2, b_ih2, b_hh2,
                               w_lin, b_lin, out);
}

// round 4
// speedup vs baseline: 1.0033x; 1.0033x over previous
#include <cuda_runtime.h>
#include <cuda_bf16.h>

#define BB   512
#define LL   1000
#define HH   128
#define NCTA 86
#define NT   256
#define MR   6

typedef unsigned long long ull;

__device__ __forceinline__ ull ffma2(ull a, ull b, ull c) {
    ull d;
    asm("fma.rn.f32x2 %0, %1, %2, %3;" : "=l"(d) : "l"(a), "l"(b), "l"(c));
    return d;
}
__device__ __forceinline__ float flo(ull v) { return __uint_as_float((unsigned)v); }
__device__ __forceinline__ float fhi(ull v) { return __uint_as_float((unsigned)(v >> 32)); }

__device__ __forceinline__ float sig_(float x) {
    float e, r;
    asm("ex2.approx.f32 %0, %1;" : "=f"(e) : "f"(-1.4426950408889634f * x));
    asm("rcp.approx.f32 %0, %1;" : "=f"(r) : "f"(1.0f + e));
    return r;
}
__device__ __forceinline__ float tnh_(float x) { return fmaf(2.0f, sig_(2.0f * x), -1.0f); }

__global__ void __launch_bounds__(NT, 1) lstm_persist(
    const float* __restrict__ x,
    const float* __restrict__ w_ih1, const float* __restrict__ w_hh1,
    const float* __restrict__ b_ih1, const float* __restrict__ b_hh1,
    const float* __restrict__ w_ih2, const float* __restrict__ w_hh2,
    const float* __restrict__ b_ih2, const float* __restrict__ b_hh2,
    const float* __restrict__ w_lin, const float* __restrict__ b_lin,
    float* __restrict__ out)
{
    __shared__ __align__(16) float h1s[MR][HH];
    __shared__ __align__(16) float h2s[MR][HH];
    __shared__ __align__(16) float gbuf[MR][4 * HH];
    __shared__ float bs1[4 * HH], bs2[4 * HH], wi1[4 * HH], wls[HH], xs[MR];

    const int tid  = threadIdx.x;
    const int row0 = blockIdx.x * MR;

    for (int i = tid; i < 4 * HH; i += NT) {
        bs1[i] = b_ih1[i] + b_hh1[i];
        bs2[i] = b_ih2[i] + b_hh2[i];
        wi1[i] = w_ih1[i];
    }
    for (int i = tid; i < HH; i += NT) wls[i] = w_lin[i];
    for (int i = tid; i < MR * HH; i += NT) {
        (&h1s[0][0])[i] = 0.0f;
        (&h2s[0][0])[i] = 0.0f;
    }
    if (tid < MR) xs[tid] = (row0 + tid < BB) ? x[(row0 + tid) * LL] : 0.0f;

    float c1[3] = {0.f, 0.f, 0.f};
    float c2[3] = {0.f, 0.f, 0.f};
    const float blin = b_lin[0];

    const int j0 = tid, j1 = tid + NT;
    const float* wh1a = w_hh1 + j0 * HH;
    const float* wh1b = w_hh1 + j1 * HH;
    const float* wi2a = w_ih2 + j0 * HH;
    const float* wi2b = w_ih2 + j1 * HH;
    const float* wh2a = w_hh2 + j0 * HH;
    const float* wh2b = w_hh2 + j1 * HH;

    __syncthreads();

    for (int t = 0; t < LL; t++) {
        // readout for step t-1 (h2s stable until phase D of this step)
        if (t > 0 && tid < MR && row0 + tid < BB) {
            float s = blin;
#pragma unroll 8
            for (int u = 0; u < HH; u++) s = fmaf(h2s[tid][u], wls[u], s);
            out[(row0 + tid) * LL + (t - 1)] = s;
        }

        // ---- Phase A: layer-1 gates = h1 @ Whh1^T (+ wih1*x + b) ----
        {
            ull acc[2][MR];
#pragma unroll
            for (int r = 0; r < MR; r++) { acc[0][r] = 0ull; acc[1][r] = 0ull; }
#pragma unroll 4
            for (int kk = 0; kk < 16; kk++) {
                ulonglong2 ha[MR], hb[MR];
#pragma unroll
                for (int r = 0; r < MR; r++) {
                    const ulonglong2* hp = (const ulonglong2*)&h1s[r][kk * 8];
                    ha[r] = hp[0]; hb[r] = hp[1];
                }
                ulonglong2 wa0 = *(const ulonglong2*)(wh1a + kk * 8);
                ulonglong2 wa1 = *(const ulonglong2*)(wh1a + kk * 8 + 4);
                ulonglong2 wb0 = *(const ulonglong2*)(wh1b + kk * 8);
                ulonglong2 wb1 = *(const ulonglong2*)(wh1b + kk * 8 + 4);
#pragma unroll
                for (int r = 0; r < MR; r++) {
                    acc[0][r] = ffma2(wa0.x, ha[r].x, acc[0][r]);
                    acc[0][r] = ffma2(wa0.y, ha[r].y, acc[0][r]);
                    acc[0][r] = ffma2(wa1.x, hb[r].x, acc[0][r]);
                    acc[0][r] = ffma2(wa1.y, hb[r].y, acc[0][r]);
                    acc[1][r] = ffma2(wb0.x, ha[r].x, acc[1][r]);
                    acc[1][r] = ffma2(wb0.y, ha[r].y, acc[1][r]);
                    acc[1][r] = ffma2(wb1.x, hb[r].x, acc[1][r]);
                    acc[1][r] = ffma2(wb1.y, hb[r].y, acc[1][r]);
                }
            }
#pragma unroll
            for (int r = 0; r < MR; r++) {
                gbuf[r][j0] = flo(acc[0][r]) + fhi(acc[0][r]) + bs1[j0] + wi1[j0] * xs[r];
                gbuf[r][j1] = flo(acc[1][r]) + fhi(acc[1][r]) + bs1[j1] + wi1[j1] * xs[r];
            }
        }
        __syncthreads();

        // ---- Phase B: layer-1 activations ----
#pragma unroll
        for (int s = 0; s < 3; s++) {
            int idx = tid + NT * s;
            int r = idx >> 7, u = idx & (HH - 1);
            float iv = sig_(gbuf[r][u]);
            float fv = sig_(gbuf[r][HH + u]);
            float gv = tnh_(gbuf[r][2 * HH + u]);
            float ov = sig_(gbuf[r][3 * HH + u]);
            c1[s] = fmaf(fv, c1[s], iv * gv);
            h1s[r][u] = ov * tnh_(c1[s]);
        }
        __syncthreads();

        // ---- Phase C: layer-2 gates = h1 @ Wih2^T + h2 @ Whh2^T (+ b) ----
        {
            ull acc[2][MR];
#pragma unroll
            for (int r = 0; r < MR; r++) { acc[0][r] = 0ull; acc[1][r] = 0ull; }
#pragma unroll 4
            for (int kk = 0; kk < 16; kk++) {
                ulonglong2 ha[MR], hb[MR];
#pragma unroll
                for (int r = 0; r < MR; r++) {
                    const ulonglong2* hp = (const ulonglong2*)&h1s[r][kk * 8];
                    ha[r] = hp[0]; hb[r] = hp[1];
                }
                ulonglong2 wa0 = *(const ulonglong2*)(wi2a + kk * 8);
                ulonglong2 wa1 = *(const ulonglong2*)(wi2a + kk * 8 + 4);
                ulonglong2 wb0 = *(const ulonglong2*)(wi2b + kk * 8);
                ulonglong2 wb1 = *(const ulonglong2*)(wi2b + kk * 8 + 4);
#pragma unroll
                for (int r = 0; r < MR; r++) {
                    acc[0][r] = ffma2(wa0.x, ha[r].x, acc[0][r]);
                    acc[0][r] = ffma2(wa0.y, ha[r].y, acc[0][r]);
                    acc[0][r] = ffma2(wa1.x, hb[r].x, acc[0][r]);
                    acc[0][r] = ffma2(wa1.y, hb[r].y, acc[0][r]);
                    acc[1][r] = ffma2(wb0.x, ha[r].x, acc[1][r]);
                    acc[1][r] = ffma2(wb0.y, ha[r].y, acc[1][r]);
                    acc[1][r] = ffma2(wb1.x, hb[r].x, acc[1][r]);
                    acc[1][r] = ffma2(wb1.y, hb[r].y, acc[1][r]);
                }
            }
#pragma unroll 4
            for (int kk = 0; kk < 16; kk++) {
                ulonglong2 ha[MR], hb[MR];
#pragma unroll
                for (int r = 0; r < MR; r++) {
                    const ulonglong2* hp = (const ulonglong2*)&h2s[r][kk * 8];
                    ha[r] = hp[0]; hb[r] = hp[1];
                }
                ulonglong2 wa0 = *(const ulonglong2*)(wh2a + kk * 8);
                ulonglong2 wa1 = *(const ulonglong2*)(wh2a + kk * 8 + 4);
                ulonglong2 wb0 = *(const ulonglong2*)(wh2b + kk * 8);
                ulonglong2 wb1 = *(const ulonglong2*)(wh2b + kk * 8 + 4);
#pragma unroll
                for (int r = 0; r < MR; r++) {
                    acc[0][r] = ffma2(wa0.x, ha[r].x, acc[0][r]);
                    acc[0][r] = ffma2(wa0.y, ha[r].y, acc[0][r]);
                    acc[0][r] = ffma2(wa1.x, hb[r].x, acc[0][r]);
                    acc[0][r] = ffma2(wa1.y, hb[r].y, acc[0][r]);
                    acc[1][r] = ffma2(wb0.x, ha[r].x, acc[1][r]);
                    acc[1][r] = ffma2(wb0.y, ha[r].y, acc[1][r]);
                    acc[1][r] = ffma2(wb1.x, hb[r].x, acc[1][r]);
                    acc[1][r] = ffma2(wb1.y, hb[r].y, acc[1][r]);
                }
            }
#pragma unroll
            for (int r = 0; r < MR; r++) {
                gbuf[r][j0] = flo(acc[0][r]) + fhi(acc[0][r]) + bs2[j0];
                gbuf[r][j1] = flo(acc[1][r]) + fhi(acc[1][r]) + bs2[j1];
            }
        }
        __syncthreads();

        // ---- Phase D: layer-2 activations + x prefetch ----
#pragma unroll
        for (int s = 0; s < 3; s++) {
            int idx = tid + NT * s;
            int r = idx >> 7, u = idx & (HH - 1);
            float iv = sig_(gbuf[r][u]);
            float fv = sig_(gbuf[r][HH + u]);
            float gv = tnh_(gbuf[r][2 * HH + u]);
            float ov = sig_(gbuf[r][3 * HH + u]);
            c2[s] = fmaf(fv, c2[s], iv * gv);
            h2s[r][u] = ov * tnh_(c2[s]);
        }
        if (tid < MR)
            xs[tid] = (row0 + tid < BB && t + 1 < LL) ? x[(row0 + tid) * LL + t + 1] : 0.0f;
        __syncthreads();
    }

    // final readout (t = LL-1)
    if (tid < MR && row0 + tid < BB) {
        float s = blin;
#pragma unroll 8
        for (int u = 0; u < HH; u++) s = fmaf(h2s[tid][u], wls[u], s);
        out[(row0 + tid) * LL + (LL - 1)] = s;
    }
}

extern "C" void kernel_launch(void* const* d_in, const int* in_sizes, int n_in,
                              void* d_out, int out_size) {
    const float* x     = (const float*)d_in[0];
    const float* w_ih1 = (const float*)d_in[1];
    const float* w_hh1 = (const float*)d_in[2];
    const float* b_ih1 = (const float*)d_in[3];
    const float* b_hh1 = (const float*)d_in[4];
    const float* w_ih2 = (const float*)d_in[5];
    const float* w_hh2 = (const float*)d_in[6];
    const float* b_ih2 = (const float*)d_in[7];
    const float* b_hh2 = (const float*)d_in[8];
    const float* w_lin = (const float*)d_in[9];
    const float* b_lin = (const float*)d_in[10];
    float* out = (float*)d_out;

    lstm_persist<<<NCTA, NT>>>(x, w_ih1, w_hh1, b_ih1, b_hh1,
                               w_ih2, w_hh2, b_ih2, b_hh2,
                               w_lin, b_lin, out);
}

// round 5
// speedup vs baseline: 2.9211x; 2.9115x over previous
#include <cuda_runtime.h>
#include <cstdint>

#define CSIZE 4
#define NCLUS 32
#define NCTA  (CSIZE * NCLUS)
#define NT    256
#define RWS   16          // batch rows per cluster
#define HHH   128
#define LLEN  1000

// dynamic smem layout (bytes)
#define OFF_W1   0         // [128][128] f32 : W_hh1 rows (g*32+ul)
#define OFF_W2I  65536     // [128][128]     : W_ih2 rows
#define OFF_W2H  131072    // [128][128]     : W_hh2 rows
#define OFF_H1   196608    // [2][16][128]
#define OFF_H2   212992    // [16][128]
#define OFF_GB   221184    // [32][16][4]  gates staging (u,r,g)
#define OFF_BS1  229376    // [32][4]
#define OFF_BS2  229888    // [32][4]
#define OFF_WI1  230400    // [32][4]
#define OFF_WL   230912    // [128]
#define OFF_XS   231424    // [16]
#define SMEM_SZ  231488

typedef unsigned long long ull;

__device__ __forceinline__ ull ffma2(ull a, ull b, ull c) {
    ull d;
    asm("fma.rn.f32x2 %0, %1, %2, %3;" : "=l"(d) : "l"(a), "l"(b), "l"(c));
    return d;
}
__device__ __forceinline__ float flo(ull v) { return __uint_as_float((unsigned)v); }
__device__ __forceinline__ float fhi(ull v) { return __uint_as_float((unsigned)(v >> 32)); }

__device__ __forceinline__ float tanhx(float v) {
    float r; asm("tanh.approx.f32 %0, %1;" : "=f"(r) : "f"(v)); return r;
}
__device__ __forceinline__ float sigx(float v) { return fmaf(tanhx(0.5f * v), 0.5f, 0.5f); }

__device__ __forceinline__ uint32_t smem_u32(const void* p) {
    uint32_t a;
    asm("{ .reg .u64 t; cvta.to.shared.u64 t, %1; cvt.u32.u64 %0, t; }" : "=r"(a) : "l"(p));
    return a;
}
__device__ __forceinline__ uint32_t ctarank() {
    uint32_t r; asm("mov.u32 %0, %%cluster_ctarank;" : "=r"(r)); return r;
}
__device__ __forceinline__ void st_cluster_f32(uint32_t addr, uint32_t rank, float v) {
    asm volatile("{ .reg .u32 ra; mapa.shared::cluster.u32 ra, %0, %1;"
                 " st.shared::cluster.f32 [ra], %2; }"
                 :: "r"(addr), "r"(rank), "f"(v) : "memory");
}
__device__ __forceinline__ void cl_arrive() {
    asm volatile("barrier.cluster.arrive.aligned;" ::: "memory");
}
__device__ __forceinline__ void cl_wait() {
    asm volatile("barrier.cluster.wait.aligned;" ::: "memory");
}

// accumulate 8 rows: acc[g][r8] += W[(g*32+ul)][kslice] dot h[H*8+r8][kslice]
// thread k-slice: granules kh+8i (i=0..3) -> floats 4*kh+32*i .. +3
__device__ __forceinline__ void mv_accum(const float* __restrict__ W,
                                         const float* __restrict__ hb, // row-half base, stride 128
                                         int ul, int kh, ull acc[4][8])
{
    ull w[4][8];
#pragma unroll
    for (int g = 0; g < 4; g++) {
        const float* wr = W + (g * 32 + ul) * HHH;
#pragma unroll
        for (int i = 0; i < 4; i++) {
            ulonglong2 v = *(const ulonglong2*)(wr + 4 * kh + 32 * i);
            w[g][2 * i] = v.x; w[g][2 * i + 1] = v.y;
        }
    }
#pragma unroll
    for (int r8 = 0; r8 < 8; r8++) {
        const float* hr = hb + r8 * HHH;
        ull hv[8];
#pragma unroll
        for (int i = 0; i < 4; i++) {
            ulonglong2 v = *(const ulonglong2*)(hr + 4 * kh + 32 * i);
            hv[2 * i] = v.x; hv[2 * i + 1] = v.y;
        }
#pragma unroll
        for (int g = 0; g < 4; g++)
#pragma unroll
            for (int ii = 0; ii < 8; ii++)
                acc[g][r8] = ffma2(w[g][ii], hv[ii], acc[g][r8]);
    }
}

__device__ __forceinline__ void reduce_store(ull acc[4][8], float* gb, int ul, int kh, int H)
{
#pragma unroll
    for (int g = 0; g < 4; g++)
#pragma unroll
        for (int r8 = 0; r8 < 8; r8++) {
            float s = flo(acc[g][r8]) + fhi(acc[g][r8]);
            s += __shfl_xor_sync(0xffffffffu, s, 1);
            s += __shfl_xor_sync(0xffffffffu, s, 2);
            s += __shfl_xor_sync(0xffffffffu, s, 4);
            if (kh == g) gb[((ul * RWS + H * 8 + r8) << 2) + g] = s;
        }
}

__global__ void __launch_bounds__(NT, 1) __cluster_dims__(CSIZE, 1, 1)
lstm_cluster(const float* __restrict__ x,
             const float* __restrict__ w_ih1, const float* __restrict__ w_hh1,
             const float* __restrict__ b_ih1, const float* __restrict__ b_hh1,
             const float* __restrict__ w_ih2, const float* __restrict__ w_hh2,
             const float* __restrict__ b_ih2, const float* __restrict__ b_hh2,
             const float* __restrict__ w_lin, const float* __restrict__ b_lin,
             float* __restrict__ out)
{
    extern __shared__ char sm[];
    float* W1  = (float*)(sm + OFF_W1);
    float* W2I = (float*)(sm + OFF_W2I);
    float* W2H = (float*)(sm + OFF_W2H);
    float* H1  = (float*)(sm + OFF_H1);
    float* H2  = (float*)(sm + OFF_H2);
    float* GB  = (float*)(sm + OFF_GB);
    float* BS1 = (float*)(sm + OFF_BS1);
    float* BS2 = (float*)(sm + OFF_BS2);
    float* WI1 = (float*)(sm + OFF_WI1);
    float* WL  = (float*)(sm + OFF_WL);
    float* XS  = (float*)(sm + OFF_XS);

    const int tid  = threadIdx.x;
    const uint32_t rank = ctarank();
    const int clus = blockIdx.x >> 2;          // cluster id
    const int row0 = clus * RWS;               // batch rows of this cluster
    const int ubase = rank * 32;               // unit slice of this CTA

    const int lane = tid & 31;
    const int ul   = ((tid >> 5) << 2) + (lane >> 3);   // unit local 0..31
    const int kh   = lane & 7;                          // k-slice 0..7

    // ---- one-time init ----
    for (int idx = tid; idx < 128 * HHH; idx += NT) {
        int j = idx >> 7, k = idx & 127;
        int g = j >> 5, uu = j & 31;
        int gj = (g << 7) + ubase + uu;
        W1[idx]  = w_hh1[gj * HHH + k];
        W2I[idx] = w_ih2[gj * HHH + k];
        W2H[idx] = w_hh2[gj * HHH + k];
    }
    for (int idx = tid; idx < 128; idx += NT) {
        int uu = idx >> 2, g = idx & 3;
        int gj = (g << 7) + ubase + uu;
        BS1[idx] = b_ih1[gj] + b_hh1[gj];
        BS2[idx] = b_ih2[gj] + b_hh2[gj];
        WI1[idx] = w_ih1[gj];
        WL[idx]  = w_lin[idx];
    }
    for (int idx = tid; idx < 2 * RWS * HHH; idx += NT) H1[idx] = 0.0f;
    for (int idx = tid; idx < RWS * HHH; idx += NT) H2[idx] = 0.0f;

    const float blin = b_lin[0];
    const uint32_t smb = smem_u32(sm);

    // act tasks: thread handles (u,r) = task tid and tid+256
    const int uA = tid >> 4, rA = tid & 15;
    const int tB = tid + NT;
    const int uB = tB >> 4, rB = tB & 15;
    float c1a = 0.f, c1b = 0.f, c2a = 0.f, c2b = 0.f;

    __syncthreads();
    cl_arrive(); cl_wait();          // peers initialized before any DSMEM traffic

    int p = 0;
    for (int t = 0; t < LLEN; t++) {
        // x prefetch for this step
        float xv = 0.0f;
        if (tid < RWS) xv = x[(row0 + tid) * LLEN + t];

        // ---- L1 matvec: gates1 = h1[p] @ W1^T ----
        const float* h1p = H1 + p * (RWS * HHH);
#pragma unroll
        for (int H = 0; H < 2; H++) {
            ull acc[4][8];
#pragma unroll
            for (int g = 0; g < 4; g++)
#pragma unroll
                for (int r8 = 0; r8 < 8; r8++) acc[g][r8] = 0ull;
            mv_accum(W1, h1p + H * 8 * HHH, ul, kh, acc);
            reduce_store(acc, GB, ul, kh, H);
        }
        if (tid < RWS) XS[tid] = xv;
        __syncthreads();

        // ---- act1 -> write h1[1-p] to all 4 CTAs ----
        const int np = 1 - p;
        {
            float4 gv = *(float4*)(GB + ((uA * RWS + rA) << 2));
            float4 bv = *(float4*)(BS1 + (uA << 2));
            float4 wv = *(float4*)(WI1 + (uA << 2));
            float xr = XS[rA];
            float iv = sigx(fmaf(wv.x, xr, gv.x + bv.x));
            float fv = sigx(fmaf(wv.y, xr, gv.y + bv.y));
            float gg = tanhx(fmaf(wv.z, xr, gv.z + bv.z));
            float ov = sigx(fmaf(wv.w, xr, gv.w + bv.w));
            c1a = fmaf(fv, c1a, iv * gg);
            float h = ov * tanhx(c1a);
            uint32_t ad = smb + OFF_H1 + (((np * RWS + rA) * HHH + ubase + uA) << 2);
#pragma unroll
            for (int pc = 0; pc < CSIZE; pc++) st_cluster_f32(ad, pc, h);
        }
        {
            float4 gv = *(float4*)(GB + ((uB * RWS + rB) << 2));
            float4 bv = *(float4*)(BS1 + (uB << 2));
            float4 wv = *(float4*)(WI1 + (uB << 2));
            float xr = XS[rB];
            float iv = sigx(fmaf(wv.x, xr, gv.x + bv.x));
            float fv = sigx(fmaf(wv.y, xr, gv.y + bv.y));
            float gg = tanhx(fmaf(wv.z, xr, gv.z + bv.z));
            float ov = sigx(fmaf(wv.w, xr, gv.w + bv.w));
            c1b = fmaf(fv, c1b, iv * gg);
            float h = ov * tanhx(c1b);
            uint32_t ad = smb + OFF_H1 + (((np * RWS + rB) * HHH + ubase + uB) << 2);
#pragma unroll
            for (int pc = 0; pc < CSIZE; pc++) st_cluster_f32(ad, pc, h);
        }
        cl_arrive(); cl_wait();      // sync_a: h1[np] complete; h2 writes of t-1 visible

        // ---- readout of step t-1 (h2 stable between sync_a and sync_b) ----
        if (t > 0 && tid < RWS) {
            float s = blin;
            const float4* hp = (const float4*)(H2 + tid * HHH);
            const float4* wp = (const float4*)WL;
#pragma unroll 8
            for (int i = 0; i < 32; i++) {
                float4 a = hp[i], b = wp[i];
                s = fmaf(a.x, b.x, s); s = fmaf(a.y, b.y, s);
                s = fmaf(a.z, b.z, s); s = fmaf(a.w, b.w, s);
            }
            out[(row0 + tid) * LLEN + (t - 1)] = s;
        }

        // ---- L2 matvec: gates2 = h1[np] @ W2I^T + h2 @ W2H^T ----
        const float* h1n = H1 + np * (RWS * HHH);
#pragma unroll
        for (int H = 0; H < 2; H++) {
            ull acc[4][8];
#pragma unroll
            for (int g = 0; g < 4; g++)
#pragma unroll
                for (int r8 = 0; r8 < 8; r8++) acc[g][r8] = 0ull;
            mv_accum(W2I, h1n + H * 8 * HHH, ul, kh, acc);
            mv_accum(W2H, H2  + H * 8 * HHH, ul, kh, acc);
            reduce_store(acc, GB, ul, kh, H);
        }
        __syncthreads();

        // ---- act2 (results held in regs until sync_b) ----
        float h2a, h2b;
        {
            float4 gv = *(float4*)(GB + ((uA * RWS + rA) << 2));
            float4 bv = *(float4*)(BS2 + (uA << 2));
            float iv = sigx(gv.x + bv.x);
            float fv = sigx(gv.y + bv.y);
            float gg = tanhx(gv.z + bv.z);
            float ov = sigx(gv.w + bv.w);
            c2a = fmaf(fv, c2a, iv * gg);
            h2a = ov * tanhx(c2a);
        }
        {
            float4 gv = *(float4*)(GB + ((uB * RWS + rB) << 2));
            float4 bv = *(float4*)(BS2 + (uB << 2));
            float iv = sigx(gv.x + bv.x);
            float fv = sigx(gv.y + bv.y);
            float gg = tanhx(gv.z + bv.z);
            float ov = sigx(gv.w + bv.w);
            c2b = fmaf(fv, c2b, iv * gg);
            h2b = ov * tanhx(c2b);
        }
        cl_arrive(); cl_wait();      // sync_b: everyone done reading h2
        {
            uint32_t ad = smb + OFF_H2 + ((rA * HHH + ubase + uA) << 2);
#pragma unroll
            for (int pc = 0; pc < CSIZE; pc++) st_cluster_f32(ad, pc, h2a);
        }
        {
            uint32_t ad = smb + OFF_H2 + ((rB * HHH + ubase + uB) << 2);
#pragma unroll
            for (int pc = 0; pc < CSIZE; pc++) st_cluster_f32(ad, pc, h2b);
        }
        p = np;
    }

    // final readout
    cl_arrive(); cl_wait();
    if (tid < RWS) {
        float s = blin;
        const float4* hp = (const float4*)(H2 + tid * HHH);
        const float4* wp = (const float4*)WL;
#pragma unroll 8
        for (int i = 0; i < 32; i++) {
            float4 a = hp[i], b = wp[i];
            s = fmaf(a.x, b.x, s); s = fmaf(a.y, b.y, s);
            s = fmaf(a.z, b.z, s); s = fmaf(a.w, b.w, s);
        }
        out[(row0 + tid) * LLEN + (LLEN - 1)] = s;
    }
}

extern "C" void kernel_launch(void* const* d_in, const int* in_sizes, int n_in,
                              void* d_out, int out_size) {
    cudaFuncSetAttribute(lstm_cluster, cudaFuncAttributeMaxDynamicSharedMemorySize, SMEM_SZ);

    const float* x     = (const float*)d_in[0];
    const float* w_ih1 = (const float*)d_in[1];
    const float* w_hh1 = (const float*)d_in[2];
    const float* b_ih1 = (const float*)d_in[3];
    const float* b_hh1 = (const float*)d_in[4];
    const float* w_ih2 = (const float*)d_in[5];
    const float* w_hh2 = (const float*)d_in[6];
    const float* b_ih2 = (const float*)d_in[7];
    const float* b_hh2 = (const float*)d_in[8];
    const float* w_lin = (const float*)d_in[9];
    const float* b_lin = (const float*)d_in[10];
    float* out = (float*)d_out;

    lstm_cluster<<<NCTA, NT, SMEM_SZ>>>(x, w_ih1, w_hh1, b_ih1, b_hh1,
                                        w_ih2, w_hh2, b_ih2, b_hh2,
                                        w_lin, b_lin, out);
}